// round 3
// baseline (speedup 1.0000x reference)
#include <cuda_runtime.h>
#include <cuda_bf16.h>
#include <math.h>
#include <stdint.h>

// Problem constants
#define DD    2560
#define HDIM  320
#define NH    8
#define SEGL  1024
#define STOT  4096
#define BATCH 2
#define MMEM  128
#define NSEG  4
#define BKT   32          // GEMM K tile

// ---------------- fp32 scratch ----------------------------------------------
__device__ float g_qr  [BATCH*SEGL*DD];
__device__ float g_ctx [BATCH*SEGL*DD];
__device__ float g_gate[BATCH*SEGL*DD];
__device__ float g_kw  [BATCH*SEGL*DD];
__device__ float g_vw  [BATCH*SEGL*DD];
__device__ float g_memA[BATCH*MMEM*DD];
__device__ float g_memB[BATCH*MMEM*DD];
__device__ float g_kr  [BATCH*MMEM*DD];
__device__ float g_vr  [BATCH*MMEM*DD];
__device__ float g_qw  [BATCH*MMEM*DD];
__device__ float g_aw  [BATCH*MMEM*DD];
__device__ float g_nm  [BATCH*MMEM*DD];
__device__ float g_cat [BATCH*MMEM*2*DD];

// ---------------- bf16 split scratch (16B aligned for cp.async) -------------
#define WMAT (DD*DD)                    // 6,553,600
#define WTOT (9*WMAT + 2*WMAT)          // 9 DxD + one 2DxD = 72,089,600
__device__ __align__(16) __nv_bfloat16 g_whi[WTOT];
__device__ __align__(16) __nv_bfloat16 g_wlo[WTOT];
__device__ __align__(16) __nv_bfloat16 g_ahi[BATCH*SEGL*DD];
__device__ __align__(16) __nv_bfloat16 g_alo[BATCH*SEGL*DD];
__device__ __align__(16) __nv_bfloat16 g_chi[BATCH*SEGL*DD];
__device__ __align__(16) __nv_bfloat16 g_clo[BATCH*SEGL*DD];
__device__ __align__(16) __nv_bfloat16 g_shi[BATCH*MMEM*2*DD];
__device__ __align__(16) __nv_bfloat16 g_slo[BATCH*MMEM*2*DD];

// weight offsets (elements)
#define OW_QR (0LL*WMAT)
#define OW_KR (1LL*WMAT)
#define OW_VR (2LL*WMAT)
#define OW_OR (3LL*WMAT)
#define OW_GR (4LL*WMAT)
#define OW_QW (5LL*WMAT)
#define OW_KW (6LL*WMAT)
#define OW_VW (7LL*WMAT)
#define OW_OW (8LL*WMAT)
#define OW_GW (9LL*WMAT)

// ---------------- PTX helpers -----------------------------------------------
__device__ __forceinline__ void cp16(uint32_t s, const void* g) {
    asm volatile("cp.async.cg.shared.global [%0], [%1], 16;\n" :: "r"(s), "l"(g));
}
__device__ __forceinline__ void cp_commit() {
    asm volatile("cp.async.commit_group;\n");
}
__device__ __forceinline__ void ldsm4(uint32_t& r0, uint32_t& r1, uint32_t& r2,
                                      uint32_t& r3, uint32_t a) {
    asm volatile("ldmatrix.sync.aligned.m8n8.x4.shared.b16 {%0,%1,%2,%3}, [%4];"
                 : "=r"(r0), "=r"(r1), "=r"(r2), "=r"(r3) : "r"(a));
}
__device__ __forceinline__ void ldsm4t(uint32_t& r0, uint32_t& r1, uint32_t& r2,
                                       uint32_t& r3, uint32_t a) {
    asm volatile("ldmatrix.sync.aligned.m8n8.x4.trans.shared.b16 {%0,%1,%2,%3}, [%4];"
                 : "=r"(r0), "=r"(r1), "=r"(r2), "=r"(r3) : "r"(a));
}
__device__ __forceinline__ void mma16816(float* c, const uint32_t* a, const uint32_t* b) {
    asm volatile("mma.sync.aligned.m16n8k16.row.col.f32.bf16.bf16.f32 "
                 "{%0,%1,%2,%3}, {%4,%5,%6,%7}, {%8,%9}, {%0,%1,%2,%3};"
                 : "+f"(c[0]), "+f"(c[1]), "+f"(c[2]), "+f"(c[3])
                 : "r"(a[0]), "r"(a[1]), "r"(a[2]), "r"(a[3]),
                   "r"(b[0]), "r"(b[1]));
}
__device__ __forceinline__ float sigmoidf_(float x) {
    return 1.0f / (1.0f + __expf(-x));
}

// ---------------- split kernel: fp32 -> bf16 hi/lo (optional row chunking) --
__global__ void split2d(const float* __restrict__ x, __nv_bfloat16* __restrict__ hi,
                        __nv_bfloat16* __restrict__ lo, int Kd, int a_cr,
                        long long a_cs) {
    const int m = blockIdx.y;
    const int k = blockIdx.x * blockDim.x + threadIdx.x;
    if (k >= Kd) return;
    const long long srow = (long long)(m / a_cr) * a_cs + (m % a_cr);
    const float v = x[srow * (long long)Kd + k];
    const __nv_bfloat16 h = __float2bfloat16(v);
    const float r = v - __bfloat162float(h);
    const long long o = (long long)m * Kd + k;
    hi[o] = h;
    lo[o] = __float2bfloat16(r);
}

// ---------------- bf16-split tensor-core GEMM -------------------------------
// C(M,N) = (Ah+Al)(Wh) + Ah(Wl), fp32 accumulate.
// A dense (M,K) bf16. W (K,N) bf16. C rows chunk-mapped: (m/c_cr)*c_cs + m%c_cr.
// EPI 0: C = acc
// EPI 1: C = sigmoid(acc + aux0[n])
// EPI 2: C = aux1[ci] + aux2[li]*acc
// EPI 3: s = sigmoid(acc + aux0[n]); C = s*aux1[ci] + (1-s)*aux2[ci]
template<int BM, int BN, int WM, int WN, int EPI>
__global__ void __launch_bounds__(256)
mma_gemm(const __nv_bfloat16* __restrict__ Ah, const __nv_bfloat16* __restrict__ Al,
         const __nv_bfloat16* __restrict__ Wh, const __nv_bfloat16* __restrict__ Wl,
         float* __restrict__ C, int M, int N, int K,
         int c_cr, long long c_cs,
         const float* __restrict__ aux0, const float* __restrict__ aux1,
         const float* __restrict__ aux2) {
    constexpr int A_ROWB = BKT * 2 + 16;           // 80 bytes, conflict-free
    constexpr int B_ROWB = BN * 2 + 16;            // 272 bytes
    constexpr int A_TILE = BM * A_ROWB;
    constexpr int B_TILE = BKT * B_ROWB;
    constexpr int STAGE  = 2 * A_TILE + 2 * B_TILE;
    constexpr int MT = WM / 16, NT = WN / 8;
    constexpr int WN_CNT = BN / WN;

    extern __shared__ char smem_raw[];
    const uint32_t sbase = (uint32_t)__cvta_generic_to_shared(smem_raw);

    const int tid  = threadIdx.x;
    const int m0   = blockIdx.y * BM;
    const int n0   = blockIdx.x * BN;
    const int warp = tid >> 5, lane = tid & 31;
    const int wid_m = warp / WN_CNT, wid_n = warp % WN_CNT;

    float acc[MT][NT][4];
#pragma unroll
    for (int i = 0; i < MT; ++i)
#pragma unroll
        for (int j = 0; j < NT; ++j)
#pragma unroll
            for (int e = 0; e < 4; ++e) acc[i][j][e] = 0.0f;

    const int NKI = K / BKT;

    auto load_stage = [&](int ks, int st) {
        const int k0 = ks * BKT;
        const uint32_t sb = sbase + st * STAGE;
#pragma unroll
        for (int t = 0; t < (BM * 4) / 256; ++t) {
            const int c = tid + t * 256;
            const int r = c >> 2, kc = (c & 3) * 8;
            const uint32_t off = r * A_ROWB + kc * 2;
            const long long gi = (long long)(m0 + r) * K + k0 + kc;
            cp16(sb + off, Ah + gi);
            cp16(sb + A_TILE + off, Al + gi);
        }
#pragma unroll
        for (int t = 0; t < 2; ++t) {
            const int c = tid + t * 256;
            const int r = c >> 4, nc = (c & 15) * 8;
            const uint32_t off = 2 * A_TILE + r * B_ROWB + nc * 2;
            const long long gi = (long long)(k0 + r) * N + n0 + nc;
            cp16(sb + off, Wh + gi);
            cp16(sb + B_TILE + off, Wl + gi);
        }
        cp_commit();
    };

    load_stage(0, 0);
    load_stage(1, 1);

    for (int ks = 0; ks < NKI; ++ks) {
        if (ks < NKI - 1) {
            asm volatile("cp.async.wait_group 1;\n");
        } else {
            asm volatile("cp.async.wait_group 0;\n");
        }
        __syncthreads();
        const uint32_t sb = sbase + (ks % 3) * STAGE;

#pragma unroll
        for (int kk = 0; kk < BKT; kk += 16) {
            uint32_t ah[MT][4], al[MT][4], bh[NT][2], bl[NT][2];
            const int arow = wid_m * WM + (lane & 15);
            const int acol = kk + (lane >> 4) * 8;
#pragma unroll
            for (int i = 0; i < MT; ++i) {
                const uint32_t ad = sb + (arow + i * 16) * A_ROWB + acol * 2;
                ldsm4(ah[i][0], ah[i][1], ah[i][2], ah[i][3], ad);
                ldsm4(al[i][0], al[i][1], al[i][2], al[i][3], ad + A_TILE);
            }
            const int brow = kk + (lane & 15);
#pragma unroll
            for (int j2 = 0; j2 < NT / 2; ++j2) {
                const int bcol = wid_n * WN + j2 * 16 + (lane >> 4) * 8;
                const uint32_t bd = sb + 2 * A_TILE + brow * B_ROWB + bcol * 2;
                ldsm4t(bh[2*j2][0], bh[2*j2][1], bh[2*j2+1][0], bh[2*j2+1][1], bd);
                ldsm4t(bl[2*j2][0], bl[2*j2][1], bl[2*j2+1][0], bl[2*j2+1][1],
                       bd + B_TILE);
            }
#pragma unroll
            for (int i = 0; i < MT; ++i)
#pragma unroll
                for (int j = 0; j < NT; ++j) {
                    mma16816(acc[i][j], ah[i], bh[j]);
                    mma16816(acc[i][j], al[i], bh[j]);
                    mma16816(acc[i][j], ah[i], bl[j]);
                }
        }
        if (ks + 2 < NKI) load_stage(ks + 2, (ks + 2) % 3);
    }

    // -------- epilogue --------
    const int gid = lane >> 2, tig = lane & 3;
    const long long crow0 = (long long)(m0 / c_cr) * c_cs + (m0 % c_cr);

    auto epival = [&](float a, long long ci, long long li, int col) -> float {
        if (EPI == 0) return a;
        if (EPI == 1) return sigmoidf_(a + aux0[col]);
        if (EPI == 2) return aux1[ci] + aux2[li] * a;
        float s = sigmoidf_(a + aux0[col]);
        return s * aux1[ci] + (1.0f - s) * aux2[ci];
    };

#pragma unroll
    for (int i = 0; i < MT; ++i) {
        const int r = wid_m * WM + i * 16 + gid;
#pragma unroll
        for (int j = 0; j < NT; ++j) {
            const int col = n0 + wid_n * WN + j * 8 + 2 * tig;
#pragma unroll
            for (int half = 0; half < 2; ++half) {
                const int rr = r + half * 8;
                const long long ci = (crow0 + rr) * (long long)N + col;
                const long long li = (long long)(m0 + rr) * N + col;
                float2 v;
                v.x = epival(acc[i][j][2 * half + 0], ci, li, col);
                v.y = epival(acc[i][j][2 * half + 1], ci + 1, li + 1, col + 1);
                *reinterpret_cast<float2*>(C + ci) = v;
            }
        }
    }
}

// ---------------- attention: one block per (q, head, batch) -----------------
__global__ void attn_k(const float* __restrict__ Q, const float* __restrict__ Km,
                       const float* __restrict__ V, float* __restrict__ O,
                       int Lq, int Lk, float scale) {
    const int q = blockIdx.x, h = blockIdx.y, b = blockIdx.z;
    const int tid = threadIdx.x;

    __shared__ float qs[HDIM];
    __shared__ float sc[1024];
    __shared__ float red[128];

    const float* qp = Q + ((long long)(b * Lq + q)) * DD + h * HDIM;
    for (int d = tid; d < HDIM; d += 128) qs[d] = qp[d];
    __syncthreads();

    const float4* q4 = reinterpret_cast<const float4*>(qs);

    float lmax = -1e30f;
    for (int j = tid; j < Lk; j += 128) {
        const float4* k4 = reinterpret_cast<const float4*>(
            Km + ((long long)(b * Lk + j)) * DD + h * HDIM);
        float s = 0.0f;
#pragma unroll 8
        for (int d = 0; d < HDIM / 4; ++d) {
            float4 a = q4[d], kb = k4[d];
            s += a.x * kb.x + a.y * kb.y + a.z * kb.z + a.w * kb.w;
        }
        s *= scale;
        sc[j] = s;
        lmax = fmaxf(lmax, s);
    }
    red[tid] = lmax;
    __syncthreads();
    for (int o = 64; o > 0; o >>= 1) {
        if (tid < o) red[tid] = fmaxf(red[tid], red[tid + o]);
        __syncthreads();
    }
    const float gmax = red[0];
    __syncthreads();

    float lsum = 0.0f;
    for (int j = tid; j < Lk; j += 128) {
        float e = __expf(sc[j] - gmax);
        sc[j] = e;
        lsum += e;
    }
    red[tid] = lsum;
    __syncthreads();
    for (int o = 64; o > 0; o >>= 1) {
        if (tid < o) red[tid] += red[tid + o];
        __syncthreads();
    }
    const float inv = 1.0f / red[0];
    __syncthreads();

    float* op = O + ((long long)(b * Lq + q)) * DD + h * HDIM;
    for (int d = tid; d < HDIM; d += 128) {
        float acc = 0.0f;
        const float* vp = V + ((long long)b * Lk) * DD + h * HDIM + d;
        for (int j = 0; j < Lk; ++j) acc += sc[j] * vp[(long long)j * DD];
        op[d] = acc * inv;
    }
}

// ---------------- concat [mem, new_mem] -------------------------------------
__global__ void concat_k(const float* __restrict__ a, const float* __restrict__ b,
                         float* __restrict__ c, int rows, int d) {
    int idx = blockIdx.x * blockDim.x + threadIdx.x;
    int total = rows * 2 * d;
    if (idx >= total) return;
    int r = idx / (2 * d);
    int col = idx % (2 * d);
    c[idx] = (col < d) ? a[(long long)r * d + col] : b[(long long)r * d + col - d];
}

// ---------------- host orchestration ----------------------------------------
extern "C" void kernel_launch(void* const* d_in, const int* in_sizes, int n_in,
                              void* d_out, int out_size) {
    const float* hid      = (const float*)d_in[0];
    const float* init_mem = (const float*)d_in[1];
    const float* wq_r     = (const float*)d_in[2];
    const float* wk_r     = (const float*)d_in[3];
    const float* wv_r     = (const float*)d_in[4];
    const float* wo_r     = (const float*)d_in[5];
    const float* wg_r     = (const float*)d_in[6];
    const float* bg_r     = (const float*)d_in[7];
    const float* wqueries = (const float*)d_in[8];
    const float* wq_w     = (const float*)d_in[9];
    const float* wk_w     = (const float*)d_in[10];
    const float* wv_w     = (const float*)d_in[11];
    const float* wo_w     = (const float*)d_in[12];
    const float* wg_w     = (const float*)d_in[13];
    const float* bg_w     = (const float*)d_in[14];
    float* out = (float*)d_out;

    float *qr, *ctx, *gate, *kw, *vw, *memA, *memB, *kr, *vr, *qw, *aw, *nm, *cat;
    __nv_bfloat16 *whi, *wlo, *ahi, *alo, *chi, *clo, *shi, *slo;
    cudaGetSymbolAddress((void**)&qr,   g_qr);
    cudaGetSymbolAddress((void**)&ctx,  g_ctx);
    cudaGetSymbolAddress((void**)&gate, g_gate);
    cudaGetSymbolAddress((void**)&kw,   g_kw);
    cudaGetSymbolAddress((void**)&vw,   g_vw);
    cudaGetSymbolAddress((void**)&memA, g_memA);
    cudaGetSymbolAddress((void**)&memB, g_memB);
    cudaGetSymbolAddress((void**)&kr,   g_kr);
    cudaGetSymbolAddress((void**)&vr,   g_vr);
    cudaGetSymbolAddress((void**)&qw,   g_qw);
    cudaGetSymbolAddress((void**)&aw,   g_aw);
    cudaGetSymbolAddress((void**)&nm,   g_nm);
    cudaGetSymbolAddress((void**)&cat,  g_cat);
    cudaGetSymbolAddress((void**)&whi,  g_whi);
    cudaGetSymbolAddress((void**)&wlo,  g_wlo);
    cudaGetSymbolAddress((void**)&ahi,  g_ahi);
    cudaGetSymbolAddress((void**)&alo,  g_alo);
    cudaGetSymbolAddress((void**)&chi,  g_chi);
    cudaGetSymbolAddress((void**)&clo,  g_clo);
    cudaGetSymbolAddress((void**)&shi,  g_shi);
    cudaGetSymbolAddress((void**)&slo,  g_slo);

    // dynamic smem limits for the GEMM instantiations
    constexpr int SMEM_BIG = 3 * (2 * 128 * (BKT * 2 + 16) + 2 * BKT * (128 * 2 + 16));
    constexpr int SMEM_SM  = 3 * (2 * 64  * (BKT * 2 + 16) + 2 * BKT * (128 * 2 + 16));
    cudaFuncSetAttribute(mma_gemm<128,128,64,32,0>, cudaFuncAttributeMaxDynamicSharedMemorySize, SMEM_BIG);
    cudaFuncSetAttribute(mma_gemm<128,128,64,32,1>, cudaFuncAttributeMaxDynamicSharedMemorySize, SMEM_BIG);
    cudaFuncSetAttribute(mma_gemm<128,128,64,32,2>, cudaFuncAttributeMaxDynamicSharedMemorySize, SMEM_BIG);
    cudaFuncSetAttribute(mma_gemm<64,128,32,32,0>,  cudaFuncAttributeMaxDynamicSharedMemorySize, SMEM_SM);
    cudaFuncSetAttribute(mma_gemm<64,128,32,32,3>,  cudaFuncAttributeMaxDynamicSharedMemorySize, SMEM_SM);

    const float scale = 0.05590169943749474f;  // 1/sqrt(320)
    const size_t memBytes = (size_t)MMEM * DD * sizeof(float);
    const int MBIG = BATCH * SEGL;   // 2048
    const int MSM  = BATCH * MMEM;   // 256

    dim3 gBig(DD / 128, MBIG / 128);   // (20, 16)
    dim3 gSm (DD / 128, MSM / 64);     // (20, 4)
    dim3 gQw (DD / 128, MMEM / 64);    // (20, 2)

    auto splitL = [&](const float* src, __nv_bfloat16* h, __nv_bfloat16* l,
                      int rows, int Kd, int cr, long long cs) {
        split2d<<<dim3(Kd / 256, rows), 256>>>(src, h, l, Kd, cr, cs);
    };

    // --- weight splits (dense) ---------------------------------------------
    splitL(wq_r, whi + OW_QR, wlo + OW_QR, DD, DD, DD, 0);
    splitL(wk_r, whi + OW_KR, wlo + OW_KR, DD, DD, DD, 0);
    splitL(wv_r, whi + OW_VR, wlo + OW_VR, DD, DD, DD, 0);
    splitL(wo_r, whi + OW_OR, wlo + OW_OR, DD, DD, DD, 0);
    splitL(wg_r, whi + OW_GR, wlo + OW_GR, DD, DD, DD, 0);
    splitL(wq_w, whi + OW_QW, wlo + OW_QW, DD, DD, DD, 0);
    splitL(wk_w, whi + OW_KW, wlo + OW_KW, DD, DD, DD, 0);
    splitL(wv_w, whi + OW_VW, wlo + OW_VW, DD, DD, DD, 0);
    splitL(wo_w, whi + OW_OW, wlo + OW_OW, DD, DD, DD, 0);
    splitL(wg_w, whi + OW_GW, wlo + OW_GW, 2 * DD, DD, 2 * DD, 0);

    // --- pre-loop: qw = write_queries @ wq_w, duplicated for batch ----------
    splitL(wqueries, shi, slo, MMEM, DD, MMEM, 0);
    mma_gemm<64,128,32,32,0><<<gQw, 256, SMEM_SM>>>(shi, slo, whi + OW_QW, wlo + OW_QW,
                                                    qw, MMEM, DD, DD, MMEM, 0,
                                                    nullptr, nullptr, nullptr);
    cudaMemcpyAsync(qw + (size_t)MMEM * DD, qw, memBytes, cudaMemcpyDeviceToDevice, 0);

    cudaMemcpyAsync(memB, init_mem, memBytes, cudaMemcpyDeviceToDevice, 0);
    cudaMemcpyAsync(memB + (size_t)MMEM * DD, init_mem, memBytes,
                    cudaMemcpyDeviceToDevice, 0);

    float* mem_cur = memB;

    for (int i = 0; i < NSEG; ++i) {
        const float* segp = hid + (long long)i * SEGL * DD;
        float* outp = out + (long long)i * SEGL * DD;

        // split seg (chunked rows: 1024-row chunks, stride 4096)
        splitL(segp, ahi, alo, MBIG, DD, SEGL, STOT);
        // q_r = seg @ wq_r
        mma_gemm<128,128,64,32,0><<<gBig, 256, SMEM_BIG>>>(ahi, alo,
            whi + OW_QR, wlo + OW_QR, qr, MBIG, DD, DD, MBIG, 0,
            nullptr, nullptr, nullptr);
        // gate = sigmoid(seg @ wg_r + bg_r)
        mma_gemm<128,128,64,32,1><<<gBig, 256, SMEM_BIG>>>(ahi, alo,
            whi + OW_GR, wlo + OW_GR, gate, MBIG, DD, DD, MBIG, 0,
            bg_r, nullptr, nullptr);
        // k_r, v_r = mem @ wk_r / wv_r
        splitL(mem_cur, shi, slo, MSM, DD, MSM, 0);
        mma_gemm<64,128,32,32,0><<<gSm, 256, SMEM_SM>>>(shi, slo,
            whi + OW_KR, wlo + OW_KR, kr, MSM, DD, DD, MSM, 0,
            nullptr, nullptr, nullptr);
        mma_gemm<64,128,32,32,0><<<gSm, 256, SMEM_SM>>>(shi, slo,
            whi + OW_VR, wlo + OW_VR, vr, MSM, DD, DD, MSM, 0,
            nullptr, nullptr, nullptr);
        // read attention
        attn_k<<<dim3(SEGL, NH, BATCH), 128>>>(qr, kr, vr, ctx, SEGL, MMEM, scale);
        // h = seg + gate * (ctx @ wo_r)  -> into d_out (chunked C)
        splitL(ctx, chi, clo, MBIG, DD, MBIG, 0);
        mma_gemm<128,128,64,32,2><<<gBig, 256, SMEM_BIG>>>(chi, clo,
            whi + OW_OR, wlo + OW_OR, outp, MBIG, DD, DD, SEGL, STOT,
            nullptr, segp, gate);
        // k_w, v_w = h @ wk_w / wv_w
        splitL(outp, ahi, alo, MBIG, DD, SEGL, STOT);
        mma_gemm<128,128,64,32,0><<<gBig, 256, SMEM_BIG>>>(ahi, alo,
            whi + OW_KW, wlo + OW_KW, kw, MBIG, DD, DD, MBIG, 0,
            nullptr, nullptr, nullptr);
        mma_gemm<128,128,64,32,0><<<gBig, 256, SMEM_BIG>>>(ahi, alo,
            whi + OW_VW, wlo + OW_VW, vw, MBIG, DD, DD, MBIG, 0,
            nullptr, nullptr, nullptr);
        // write attention
        attn_k<<<dim3(MMEM, NH, BATCH), 128>>>(qw, kw, vw, aw, MMEM, SEGL, scale);
        // new_mem = aw @ wo_w
        splitL(aw, shi, slo, MSM, DD, MSM, 0);
        mma_gemm<64,128,32,32,0><<<gSm, 256, SMEM_SM>>>(shi, slo,
            whi + OW_OW, wlo + OW_OW, nm, MSM, DD, DD, MSM, 0,
            nullptr, nullptr, nullptr);
        // memory update
        if (i == 0) {
            cudaMemcpyAsync(memA, nm, (size_t)MSM * DD * sizeof(float),
                            cudaMemcpyDeviceToDevice, 0);
            mem_cur = memA;
        } else {
            float* mem_next = (mem_cur == memA) ? memB : memA;
            int total = MSM * 2 * DD;
            concat_k<<<(total + 255) / 256, 256>>>(mem_cur, nm, cat, MSM, DD);
            splitL(cat, shi, slo, MSM, 2 * DD, MSM, 0);
            mma_gemm<64,128,32,32,3><<<gSm, 256, SMEM_SM>>>(shi, slo,
                whi + OW_GW, wlo + OW_GW, mem_next, MSM, DD, 2 * DD, MSM, 0,
                bg_w, nm, mem_cur);
            mem_cur = mem_next;
        }
    }
}

// round 5
// speedup vs baseline: 1.7228x; 1.7228x over previous
#include <cuda_runtime.h>
#include <cuda_bf16.h>
#include <math.h>
#include <stdint.h>
typedef __nv_bfloat16 bf16;

#define DD    2560
#define HDIM  320
#define NH    8
#define SEGL  1024
#define STOT  4096
#define BATCH 2
#define MMEM  128
#define NSEG  4
#define MBIG  (BATCH*SEGL)
#define MSM   (BATCH*MMEM)
#define BKT   32

// fp32 scratch
__device__ float g_qr[MBIG*DD], g_gate[MBIG*DD], g_kw[MBIG*DD], g_vw[MBIG*DD];
__device__ float g_kr[MSM*DD], g_vr[MSM*DD], g_qw[MSM*DD], g_nm[MSM*DD];
__device__ float g_memA[MSM*DD], g_memB[MSM*DD];
// bf16 scratch
#define WMAT (DD*DD)
__device__ __align__(16) bf16 g_whi[11LL*WMAT], g_wlo[11LL*WMAT];
__device__ __align__(16) bf16 g_hidhi[BATCH*STOT*DD], g_hidlo[BATCH*STOT*DD];
__device__ __align__(16) bf16 g_chi[MBIG*DD], g_clo[MBIG*DD];
__device__ __align__(16) bf16 g_ahi[MBIG*DD], g_alo[MBIG*DD];
__device__ __align__(16) bf16 g_awhi[MSM*DD], g_awlo[MSM*DD];
__device__ __align__(16) bf16 g_cathi[MSM*2*DD], g_catlo[MSM*2*DD];
__device__ __align__(16) bf16 g_mAhi[MSM*DD], g_mAlo[MSM*DD];
__device__ __align__(16) bf16 g_mBhi[MSM*DD], g_mBlo[MSM*DD];
__device__ __align__(16) bf16 g_imhi[MMEM*DD], g_imlo[MMEM*DD];
__device__ __align__(16) bf16 g_wqhi[MMEM*DD], g_wqlo[MMEM*DD];

#define OW_QR (0LL*WMAT)
#define OW_KR (1LL*WMAT)
#define OW_VR (2LL*WMAT)
#define OW_OR (3LL*WMAT)
#define OW_GR (4LL*WMAT)
#define OW_QW (5LL*WMAT)
#define OW_KW (6LL*WMAT)
#define OW_VW (7LL*WMAT)
#define OW_OW (8LL*WMAT)
#define OW_GW (9LL*WMAT)

__device__ __forceinline__ void cp16(uint32_t s, const void* g) {
    asm volatile("cp.async.cg.shared.global [%0], [%1], 16;\n" :: "r"(s), "l"(g));
}
__device__ __forceinline__ void ldsm4(uint32_t& r0, uint32_t& r1, uint32_t& r2,
                                      uint32_t& r3, uint32_t a) {
    asm volatile("ldmatrix.sync.aligned.m8n8.x4.shared.b16 {%0,%1,%2,%3}, [%4];"
                 : "=r"(r0), "=r"(r1), "=r"(r2), "=r"(r3) : "r"(a));
}
__device__ __forceinline__ void ldsm4t(uint32_t& r0, uint32_t& r1, uint32_t& r2,
                                       uint32_t& r3, uint32_t a) {
    asm volatile("ldmatrix.sync.aligned.m8n8.x4.trans.shared.b16 {%0,%1,%2,%3}, [%4];"
                 : "=r"(r0), "=r"(r1), "=r"(r2), "=r"(r3) : "r"(a));
}
__device__ __forceinline__ void mma16816(float* c, const uint32_t* a, const uint32_t* b) {
    asm volatile("mma.sync.aligned.m16n8k16.row.col.f32.bf16.bf16.f32 "
                 "{%0,%1,%2,%3}, {%4,%5,%6,%7}, {%8,%9}, {%0,%1,%2,%3};"
                 : "+f"(c[0]), "+f"(c[1]), "+f"(c[2]), "+f"(c[3])
                 : "r"(a[0]), "r"(a[1]), "r"(a[2]), "r"(a[3]), "r"(b[0]), "r"(b[1]));
}
__device__ __forceinline__ float sig_(float x) { return 1.0f / (1.0f + __expf(-x)); }

// ---- bf16-split HMMA GEMM: C = (Ah+Al)@Wh + Ah@Wl, fp32 accumulate --------
// A rows chunk-mapped (a_cr,a_cs). C rows chunk-mapped (c_cr,c_cs).
// EPI 0: v=acc  1: v=sig(acc+aux0[n])  2: v=aux1[ci]+aux2[li]*acc
// EPI 3: s=sig(acc+aux0[n]); v=s*aux1[li]+(1-s)*aux2[li]
// SPLIT: additionally write dense bf16 hi/lo of v at li.
template<int BM, int WM, int EPI, bool SPLIT>
__global__ void __launch_bounds__(256, 2)
mma_gemm(const bf16* __restrict__ Ah, const bf16* __restrict__ Al,
         const bf16* __restrict__ Wh, const bf16* __restrict__ Wl,
         float* __restrict__ C, bf16* __restrict__ Shi, bf16* __restrict__ Slo,
         int N, int K, int a_cr, long long a_cs, int c_cr, long long c_cs,
         const float* __restrict__ aux0, const float* __restrict__ aux1,
         const float* __restrict__ aux2) {
    constexpr int BN = 128, WN = 32;
    constexpr int A_ROWB = BKT * 2 + 16;          // 80B
    constexpr int B_ROWB = BN * 2 + 16;           // 272B
    constexpr int A_TILE = BM * A_ROWB;
    constexpr int B_TILE = BKT * B_ROWB;
    constexpr int STAGE = 2 * A_TILE + 2 * B_TILE;
    constexpr int MT = WM / 16, NT = WN / 8;

    extern __shared__ char smem_raw[];
    const uint32_t sbase = (uint32_t)__cvta_generic_to_shared(smem_raw);

    const int tid = threadIdx.x;
    const int m0 = blockIdx.y * BM, n0 = blockIdx.x * BN;
    const int warp = tid >> 5, lane = tid & 31;
    const int wid_m = warp >> 2, wid_n = warp & 3;
    const long long arow0 = (long long)(m0 / a_cr) * a_cs + (m0 % a_cr);

    float acc[MT][NT][4];
#pragma unroll
    for (int i = 0; i < MT; ++i)
#pragma unroll
        for (int j = 0; j < NT; ++j)
#pragma unroll
            for (int e = 0; e < 4; ++e) acc[i][j][e] = 0.0f;

    const int NKI = K / BKT;

    auto ldst = [&](int ks, int st) {
        const int k0 = ks * BKT;
        const uint32_t sb = sbase + st * STAGE;
#pragma unroll
        for (int t = 0; t < (BM * 4) / 256; ++t) {
            const int c = tid + t * 256;
            const int r = c >> 2, kc = (c & 3) * 8;
            const uint32_t off = r * A_ROWB + kc * 2;
            const long long gi = (arow0 + r) * (long long)K + k0 + kc;
            cp16(sb + off, Ah + gi);
            cp16(sb + A_TILE + off, Al + gi);
        }
#pragma unroll
        for (int t = 0; t < 2; ++t) {
            const int c = tid + t * 256;
            const int r = c >> 4, nc = (c & 15) * 8;
            const uint32_t off = 2 * A_TILE + r * B_ROWB + nc * 2;
            const long long gi = (long long)(k0 + r) * N + n0 + nc;
            cp16(sb + off, Wh + gi);
            cp16(sb + B_TILE + off, Wl + gi);
        }
        asm volatile("cp.async.commit_group;\n");
    };

    ldst(0, 0);
    ldst(1, 1);

    for (int ks = 0; ks < NKI; ++ks) {
        if (ks < NKI - 1) asm volatile("cp.async.wait_group 1;\n");
        else              asm volatile("cp.async.wait_group 0;\n");
        __syncthreads();
        const uint32_t sb = sbase + (ks & 1) * STAGE;

#pragma unroll
        for (int kk = 0; kk < BKT; kk += 16) {
            uint32_t ah[MT][4], al[MT][4], bh[NT][2], bl[NT][2];
            const int arow = wid_m * WM + (lane & 15);
            const int acol = kk + (lane >> 4) * 8;
#pragma unroll
            for (int i = 0; i < MT; ++i) {
                const uint32_t ad = sb + (arow + i * 16) * A_ROWB + acol * 2;
                ldsm4(ah[i][0], ah[i][1], ah[i][2], ah[i][3], ad);
                ldsm4(al[i][0], al[i][1], al[i][2], al[i][3], ad + A_TILE);
            }
            const int brow = kk + (lane & 15);
#pragma unroll
            for (int j2 = 0; j2 < NT / 2; ++j2) {
                const int bcol = wid_n * WN + j2 * 16 + (lane >> 4) * 8;
                const uint32_t bd = sb + 2 * A_TILE + brow * B_ROWB + bcol * 2;
                ldsm4t(bh[2*j2][0], bh[2*j2][1], bh[2*j2+1][0], bh[2*j2+1][1], bd);
                ldsm4t(bl[2*j2][0], bl[2*j2][1], bl[2*j2+1][0], bl[2*j2+1][1], bd + B_TILE);
            }
#pragma unroll
            for (int i = 0; i < MT; ++i)
#pragma unroll
                for (int j = 0; j < NT; ++j) {
                    mma16816(acc[i][j], ah[i], bh[j]);
                    mma16816(acc[i][j], al[i], bh[j]);
                    mma16816(acc[i][j], ah[i], bl[j]);
                }
        }
        __syncthreads();
        if (ks + 2 < NKI) ldst(ks + 2, ks & 1);
    }

    const int gid = lane >> 2, tig = lane & 3;
    const long long crow0 = (long long)(m0 / c_cr) * c_cs + (m0 % c_cr);

#pragma unroll
    for (int i = 0; i < MT; ++i) {
        const int r = wid_m * WM + i * 16 + gid;
#pragma unroll
        for (int j = 0; j < NT; ++j) {
            const int col = n0 + wid_n * WN + j * 8 + 2 * tig;
#pragma unroll
            for (int half = 0; half < 2; ++half) {
                const int rr = r + half * 8;
                const long long ci = (crow0 + rr) * (long long)N + col;
                const long long li = (long long)(m0 + rr) * N + col;
                float2 v;
#pragma unroll
                for (int e = 0; e < 2; ++e) {
                    const float a = acc[i][j][2 * half + e];
                    float o;
                    if      (EPI == 0) o = a;
                    else if (EPI == 1) o = sig_(a + aux0[col + e]);
                    else if (EPI == 2) o = aux1[ci + e] + aux2[li + e] * a;
                    else { const float s = sig_(a + aux0[col + e]);
                           o = s * aux1[li + e] + (1.0f - s) * aux2[li + e]; }
                    (&v.x)[e] = o;
                }
                *reinterpret_cast<float2*>(C + ci) = v;
                if (SPLIT) {
                    const bf16 h0 = __float2bfloat16(v.x), h1 = __float2bfloat16(v.y);
                    *reinterpret_cast<__nv_bfloat162*>(Shi + li) = __nv_bfloat162(h0, h1);
                    *reinterpret_cast<__nv_bfloat162*>(Slo + li) = __nv_bfloat162(
                        __float2bfloat16(v.x - __bfloat162float(h0)),
                        __float2bfloat16(v.y - __bfloat162float(h1)));
                }
            }
        }
    }
}

// ---- flash attention: 16 queries/block, warp w owns queries 2w, 2w+1 -------
__global__ void __launch_bounds__(256)
attn16(const float* __restrict__ Q, const float* __restrict__ Kp,
       const float* __restrict__ V, bf16* __restrict__ Ohi, bf16* __restrict__ Olo,
       int Lq, int Lk, float scale) {
    __shared__ float Ks[16][HDIM], Vs[16][HDIM];
    const int h = blockIdx.y, b = blockIdx.z, q0 = blockIdx.x * 16;
    const int tid = threadIdx.x, w = tid >> 5, l = tid & 31;
    const int qa = q0 + 2 * w;

    float qA[10], qB[10];
    const float* Qb = Q + ((long long)(b * Lq + qa)) * DD + h * HDIM;
#pragma unroll
    for (int t = 0; t < 10; ++t) { qA[t] = Qb[l + 32 * t]; qB[t] = Qb[DD + l + 32 * t]; }

    float mrun = -1e30f, sA = 0.0f, sB = 0.0f, accA[10], accB[10];
#pragma unroll
    for (int t = 0; t < 10; ++t) { accA[t] = 0.0f; accB[t] = 0.0f; }

    for (int c = 0; c < Lk / 16; ++c) {
        const long long k0 = (long long)(b * Lk + c * 16) * DD + h * HDIM;
#pragma unroll
        for (int t = 0; t < 5; ++t) {
            const int idx = tid + t * 256;
            const int row = idx / 80, c4 = idx % 80;
            *reinterpret_cast<float4*>(&Ks[row][c4 * 4]) =
                *reinterpret_cast<const float4*>(Kp + k0 + (long long)row * DD + c4 * 4);
            *reinterpret_cast<float4*>(&Vs[row][c4 * 4]) =
                *reinterpret_cast<const float4*>(V + k0 + (long long)row * DD + c4 * 4);
        }
        __syncthreads();
        float scA[16], scB[16], cmax = -1e30f;
#pragma unroll
        for (int k = 0; k < 16; ++k) {
            float da = 0.0f, db = 0.0f;
#pragma unroll
            for (int t = 0; t < 10; ++t) {
                const float kv = Ks[k][l + 32 * t];
                da += qA[t] * kv; db += qB[t] * kv;
            }
#pragma unroll
            for (int o = 16; o > 0; o >>= 1) {
                da += __shfl_xor_sync(0xFFFFFFFF, da, o);
                db += __shfl_xor_sync(0xFFFFFFFF, db, o);
            }
            scA[k] = da * scale; scB[k] = db * scale;
            cmax = fmaxf(cmax, fmaxf(scA[k], scB[k]));
        }
        const float mn = fmaxf(mrun, cmax);
        const float cr = __expf(mrun - mn);
        sA *= cr; sB *= cr;
#pragma unroll
        for (int t = 0; t < 10; ++t) { accA[t] *= cr; accB[t] *= cr; }
        mrun = mn;
#pragma unroll
        for (int k = 0; k < 16; ++k) {
            const float pa = __expf(scA[k] - mn), pb = __expf(scB[k] - mn);
            sA += pa; sB += pb;
#pragma unroll
            for (int t = 0; t < 10; ++t) {
                const float vv = Vs[k][l + 32 * t];
                accA[t] += pa * vv; accB[t] += pb * vv;
            }
        }
        __syncthreads();
    }
    const float iA = 1.0f / sA, iB = 1.0f / sB;
    bf16* Oh = Ohi + ((long long)(b * Lq + qa)) * DD + h * HDIM;
    bf16* Ol = Olo + ((long long)(b * Lq + qa)) * DD + h * HDIM;
#pragma unroll
    for (int t = 0; t < 10; ++t) {
        const float va = accA[t] * iA, vb = accB[t] * iB;
        const bf16 ha = __float2bfloat16(va), hb = __float2bfloat16(vb);
        Oh[l + 32 * t] = ha;      Ol[l + 32 * t] = __float2bfloat16(va - __bfloat162float(ha));
        Oh[DD + l + 32 * t] = hb; Ol[DD + l + 32 * t] = __float2bfloat16(vb - __bfloat162float(hb));
    }
}

__global__ void split_id(const float* __restrict__ x, bf16* __restrict__ hi,
                         bf16* __restrict__ lo) {
    const long long o = (long long)blockIdx.x * 256 + threadIdx.x;
    const float v = x[o];
    const bf16 h = __float2bfloat16(v);
    hi[o] = h; lo[o] = __float2bfloat16(v - __bfloat162float(h));
}

__global__ void wsplit(const float* __restrict__ W, bf16* __restrict__ hi,
                       bf16* __restrict__ lo) {
    const long long o = (long long)blockIdx.x * 256 + threadIdx.x;
    const float v = W[o];
    const bf16 h = __float2bfloat16(v);
    hi[o] = h; lo[o] = __float2bfloat16(v - __bfloat162float(h));
}

__global__ void concat_split(const float* __restrict__ mem, const float* __restrict__ nm,
                             bf16* __restrict__ hi, bf16* __restrict__ lo) {
    const long long idx = (long long)blockIdx.x * 256 + threadIdx.x;
    const long long r = idx / (2 * DD);
    const int c = (int)(idx % (2 * DD));
    const float v = (c < DD) ? mem[r * DD + c] : nm[r * DD + c - DD];
    const bf16 h = __float2bfloat16(v);
    hi[idx] = h; lo[idx] = __float2bfloat16(v - __bfloat162float(h));
}

extern "C" void kernel_launch(void* const* d_in, const int* in_sizes, int n_in,
                              void* d_out, int out_size) {
    const float* hid      = (const float*)d_in[0];
    const float* init_mem = (const float*)d_in[1];
    const float* wq_r = (const float*)d_in[2];
    const float* wk_r = (const float*)d_in[3];
    const float* wv_r = (const float*)d_in[4];
    const float* wo_r = (const float*)d_in[5];
    const float* wg_r = (const float*)d_in[6];
    const float* bg_r = (const float*)d_in[7];
    const float* wqueries = (const float*)d_in[8];
    const float* wq_w = (const float*)d_in[9];
    const float* wk_w = (const float*)d_in[10];
    const float* wv_w = (const float*)d_in[11];
    const float* wo_w = (const float*)d_in[12];
    const float* wg_w = (const float*)d_in[13];
    const float* bg_w = (const float*)d_in[14];
    float* out = (float*)d_out;

    float *qr, *gate, *kw, *vw, *kr, *vr, *qw, *nm, *memA, *memB;
    bf16 *whi, *wlo, *hidhi, *hidlo, *chi, *clo, *ahi, *alo, *awhi, *awlo;
    bf16 *cathi, *catlo, *mAhi, *mAlo, *mBhi, *mBlo, *imhi, *imlo, *wqhi, *wqlo;
    cudaGetSymbolAddress((void**)&qr, g_qr);     cudaGetSymbolAddress((void**)&gate, g_gate);
    cudaGetSymbolAddress((void**)&kw, g_kw);     cudaGetSymbolAddress((void**)&vw, g_vw);
    cudaGetSymbolAddress((void**)&kr, g_kr);     cudaGetSymbolAddress((void**)&vr, g_vr);
    cudaGetSymbolAddress((void**)&qw, g_qw);     cudaGetSymbolAddress((void**)&nm, g_nm);
    cudaGetSymbolAddress((void**)&memA, g_memA); cudaGetSymbolAddress((void**)&memB, g_memB);
    cudaGetSymbolAddress((void**)&whi, g_whi);   cudaGetSymbolAddress((void**)&wlo, g_wlo);
    cudaGetSymbolAddress((void**)&hidhi, g_hidhi); cudaGetSymbolAddress((void**)&hidlo, g_hidlo);
    cudaGetSymbolAddress((void**)&chi, g_chi);   cudaGetSymbolAddress((void**)&clo, g_clo);
    cudaGetSymbolAddress((void**)&ahi, g_ahi);   cudaGetSymbolAddress((void**)&alo, g_alo);
    cudaGetSymbolAddress((void**)&awhi, g_awhi); cudaGetSymbolAddress((void**)&awlo, g_awlo);
    cudaGetSymbolAddress((void**)&cathi, g_cathi); cudaGetSymbolAddress((void**)&catlo, g_catlo);
    cudaGetSymbolAddress((void**)&mAhi, g_mAhi); cudaGetSymbolAddress((void**)&mAlo, g_mAlo);
    cudaGetSymbolAddress((void**)&mBhi, g_mBhi); cudaGetSymbolAddress((void**)&mBlo, g_mBlo);
    cudaGetSymbolAddress((void**)&imhi, g_imhi); cudaGetSymbolAddress((void**)&imlo, g_imlo);
    cudaGetSymbolAddress((void**)&wqhi, g_wqhi); cudaGetSymbolAddress((void**)&wqlo, g_wqlo);

    constexpr int SMEM_BIG = 2 * (2 * 128 * 80 + 2 * 32 * 272);   // 75776
    constexpr int SMEM_SM  = 2 * (2 * 64  * 80 + 2 * 32 * 272);   // 55296
    cudaFuncSetAttribute(mma_gemm<128,64,0,false>, cudaFuncAttributeMaxDynamicSharedMemorySize, SMEM_BIG);
    cudaFuncSetAttribute(mma_gemm<128,64,1,false>, cudaFuncAttributeMaxDynamicSharedMemorySize, SMEM_BIG);
    cudaFuncSetAttribute(mma_gemm<128,64,2,true >, cudaFuncAttributeMaxDynamicSharedMemorySize, SMEM_BIG);
    cudaFuncSetAttribute(mma_gemm<64,32,0,false>,  cudaFuncAttributeMaxDynamicSharedMemorySize, SMEM_SM);
    cudaFuncSetAttribute(mma_gemm<64,32,0,true >,  cudaFuncAttributeMaxDynamicSharedMemorySize, SMEM_SM);
    cudaFuncSetAttribute(mma_gemm<64,32,3,true >,  cudaFuncAttributeMaxDynamicSharedMemorySize, SMEM_SM);

    const float scale = 0.05590169943749474f;
    const size_t memBytesF = (size_t)MMEM * DD * sizeof(float);
    dim3 gBig(DD / 128, MBIG / 128);   // (20,16)
    dim3 gSm (DD / 128, MSM / 64);     // (20,4)
    dim3 gQw (DD / 128, 1);

    // weight splits (kept in (K,N) layout, consumed column-major by ldsm4t)
    wsplit<<<(WMAT)/256,256>>>(wq_r, whi+OW_QR, wlo+OW_QR);
    wsplit<<<(WMAT)/256,256>>>(wk_r, whi+OW_KR, wlo+OW_KR);
    wsplit<<<(WMAT)/256,256>>>(wv_r, whi+OW_VR, wlo+OW_VR);
    wsplit<<<(WMAT)/256,256>>>(wo_r, whi+OW_OR, wlo+OW_OR);
    wsplit<<<(WMAT)/256,256>>>(wg_r, whi+OW_GR, wlo+OW_GR);
    wsplit<<<(WMAT)/256,256>>>(wq_w, whi+OW_QW, wlo+OW_QW);
    wsplit<<<(WMAT)/256,256>>>(wk_w, whi+OW_KW, wlo+OW_KW);
    wsplit<<<(WMAT)/256,256>>>(wv_w, whi+OW_VW, wlo+OW_VW);
    wsplit<<<(WMAT)/256,256>>>(wo_w, whi+OW_OW, wlo+OW_OW);
    wsplit<<<(2*WMAT)/256,256>>>(wg_w, whi+OW_GW, wlo+OW_GW);

    split_id<<<(BATCH*STOT*DD)/256,256>>>(hid, hidhi, hidlo);
    split_id<<<(MMEM*DD)/256,256>>>(init_mem, imhi, imlo);
    split_id<<<(MMEM*DD)/256,256>>>(wqueries, wqhi, wqlo);

    // qw = write_queries @ wq_w (M=128), duplicate for batch
    mma_gemm<128,64,0,false><<<gQw,256,SMEM_BIG>>>(wqhi, wqlo, whi+OW_QW, wlo+OW_QW,
        qw, nullptr, nullptr, DD, DD, MMEM, 0, MMEM, 0, nullptr, nullptr, nullptr);
    cudaMemcpyAsync(qw + (size_t)MMEM*DD, qw, memBytesF, cudaMemcpyDeviceToDevice, 0);

    float* memf[2] = {memA, memB};
    bf16*  memh[2] = {mAhi, mBhi};
    bf16*  meml[2] = {mAlo, mBlo};
    int cur = 0;

    for (int i = 0; i < NSEG; ++i) {
        const float* segp = hid + (long long)i * SEGL * DD;
        float* outp = out + (long long)i * SEGL * DD;
        const bf16* shi = hidhi + (long long)i * SEGL * DD;
        const bf16* slo = hidlo + (long long)i * SEGL * DD;

        mma_gemm<128,64,0,false><<<gBig,256,SMEM_BIG>>>(shi, slo, whi+OW_QR, wlo+OW_QR,
            qr, nullptr, nullptr, DD, DD, SEGL, (long long)STOT*1, MBIG, 0, nullptr, nullptr, nullptr);
        mma_gemm<128,64,1,false><<<gBig,256,SMEM_BIG>>>(shi, slo, whi+OW_GR, wlo+OW_GR,
            gate, nullptr, nullptr, DD, DD, SEGL, (long long)STOT*1, MBIG, 0, bg_r, nullptr, nullptr);

        const bf16* mh = (i == 0) ? imhi : memh[cur];
        const bf16* ml = (i == 0) ? imlo : meml[cur];
        const int mcr = (i == 0) ? MMEM : MSM;
        mma_gemm<64,32,0,false><<<gSm,256,SMEM_SM>>>(mh, ml, whi+OW_KR, wlo+OW_KR,
            kr, nullptr, nullptr, DD, DD, mcr, 0, MSM, 0, nullptr, nullptr, nullptr);
        mma_gemm<64,32,0,false><<<gSm,256,SMEM_SM>>>(mh, ml, whi+OW_VR, wlo+OW_VR,
            vr, nullptr, nullptr, DD, DD, mcr, 0, MSM, 0, nullptr, nullptr, nullptr);

        attn16<<<dim3(SEGL/16, NH, BATCH),256>>>(qr, kr, vr, chi, clo, SEGL, MMEM, scale);

        mma_gemm<128,64,2,true><<<gBig,256,SMEM_BIG>>>(chi, clo, whi+OW_OR, wlo+OW_OR,
            outp, ahi, alo, DD, DD, MBIG, 0, SEGL, (long long)STOT*1, nullptr, segp, gate);

        mma_gemm<128,64,0,false><<<gBig,256,SMEM_BIG>>>(ahi, alo, whi+OW_KW, wlo+OW_KW,
            kw, nullptr, nullptr, DD, DD, MBIG, 0, MBIG, 0, nullptr, nullptr, nullptr);
        mma_gemm<128,64,0,false><<<gBig,256,SMEM_BIG>>>(ahi, alo, whi+OW_VW, wlo+OW_VW,
            vw, nullptr, nullptr, DD, DD, MBIG, 0, MBIG, 0, nullptr, nullptr, nullptr);

        attn16<<<dim3(MMEM/16, NH, BATCH),256>>>(qw, kw, vw, awhi, awlo, MMEM, SEGL, scale);

        if (i == 0) {
            mma_gemm<64,32,0,true><<<gSm,256,SMEM_SM>>>(awhi, awlo, whi+OW_OW, wlo+OW_OW,
                memf[0], mAhi, mAlo, DD, DD, MSM, 0, MSM, 0, nullptr, nullptr, nullptr);
            cur = 0;
        } else {
            mma_gemm<64,32,0,false><<<gSm,256,SMEM_SM>>>(awhi, awlo, whi+OW_OW, wlo+OW_OW,
                nm, nullptr, nullptr, DD, DD, MSM, 0, MSM, 0, nullptr, nullptr, nullptr);
            const int nxt = cur ^ 1;
            concat_split<<<(MSM*2*DD)/256,256>>>(memf[cur], nm, cathi, catlo);
            mma_gemm<64,32,3,true><<<gSm,256,SMEM_SM>>>(cathi, catlo, whi+OW_GW, wlo+OW_GW,
                memf[nxt], memh[nxt], meml[nxt], DD, 2*DD, MSM, 0, MSM, 0,
                bg_w, nm, memf[cur]);
            cur = nxt;
        }
    }
}

// round 6
// speedup vs baseline: 1.7942x; 1.0415x over previous
#include <cuda_runtime.h>
#include <cuda_bf16.h>
#include <math.h>
#include <stdint.h>
typedef __nv_bfloat16 bf16;

#define DD    2560
#define HDIM  320
#define NH    8
#define SEGL  1024
#define STOT  4096
#define BATCH 2
#define MMEM  128
#define NSEG  4
#define MBIG  (BATCH*SEGL)
#define MSM   (BATCH*MMEM)
#define BKT   32
#define BN    160
#define WN    80
#define NT    10

// fp32 scratch
__device__ float g_qr[MBIG*DD], g_gate[MBIG*DD], g_kw[MBIG*DD], g_vw[MBIG*DD];
__device__ float g_kr[MSM*DD], g_vr[MSM*DD], g_qw[MSM*DD], g_nm[MSM*DD];
__device__ float g_memA[MSM*DD], g_memB[MSM*DD];
// bf16 scratch
#define WMAT (DD*DD)
__device__ __align__(16) bf16 g_whi[11LL*WMAT], g_wlo[11LL*WMAT];
__device__ __align__(16) bf16 g_hidhi[BATCH*STOT*DD], g_hidlo[BATCH*STOT*DD];
__device__ __align__(16) bf16 g_chi[MBIG*DD], g_clo[MBIG*DD];
__device__ __align__(16) bf16 g_ahi[MBIG*DD], g_alo[MBIG*DD];
__device__ __align__(16) bf16 g_awhi[MSM*DD], g_awlo[MSM*DD];
__device__ __align__(16) bf16 g_cathi[MSM*2*DD], g_catlo[MSM*2*DD];
__device__ __align__(16) bf16 g_mAhi[MSM*DD], g_mAlo[MSM*DD];
__device__ __align__(16) bf16 g_mBhi[MSM*DD], g_mBlo[MSM*DD];
__device__ __align__(16) bf16 g_imhi[MMEM*DD], g_imlo[MMEM*DD];
__device__ __align__(16) bf16 g_wqhi[MMEM*DD], g_wqlo[MMEM*DD];

#define OW_QR (0LL*WMAT)
#define OW_KR (1LL*WMAT)
#define OW_VR (2LL*WMAT)
#define OW_OR (3LL*WMAT)
#define OW_GR (4LL*WMAT)
#define OW_QW (5LL*WMAT)
#define OW_KW (6LL*WMAT)
#define OW_VW (7LL*WMAT)
#define OW_OW (8LL*WMAT)
#define OW_GW (9LL*WMAT)

__device__ __forceinline__ void cp16(uint32_t s, const void* g) {
    asm volatile("cp.async.cg.shared.global [%0], [%1], 16;\n" :: "r"(s), "l"(g));
}
__device__ __forceinline__ void ldsm4(uint32_t& r0, uint32_t& r1, uint32_t& r2,
                                      uint32_t& r3, uint32_t a) {
    asm volatile("ldmatrix.sync.aligned.m8n8.x4.shared.b16 {%0,%1,%2,%3}, [%4];"
                 : "=r"(r0), "=r"(r1), "=r"(r2), "=r"(r3) : "r"(a));
}
__device__ __forceinline__ void ldsm4t(uint32_t& r0, uint32_t& r1, uint32_t& r2,
                                       uint32_t& r3, uint32_t a) {
    asm volatile("ldmatrix.sync.aligned.m8n8.x4.trans.shared.b16 {%0,%1,%2,%3}, [%4];"
                 : "=r"(r0), "=r"(r1), "=r"(r2), "=r"(r3) : "r"(a));
}
__device__ __forceinline__ void mma16816(float* c, const uint32_t* a, const uint32_t* b) {
    asm volatile("mma.sync.aligned.m16n8k16.row.col.f32.bf16.bf16.f32 "
                 "{%0,%1,%2,%3}, {%4,%5,%6,%7}, {%8,%9}, {%0,%1,%2,%3};"
                 : "+f"(c[0]), "+f"(c[1]), "+f"(c[2]), "+f"(c[3])
                 : "r"(a[0]), "r"(a[1]), "r"(a[2]), "r"(a[3]), "r"(b[0]), "r"(b[1]));
}
__device__ __forceinline__ float sig_(float x) { return 1.0f / (1.0f + __expf(-x)); }

// ---- bf16-split HMMA GEMM: C = (Ah+Al)@Wh + Ah@Wl, fp32 accumulate --------
// BM x 160 block tile; warp layout 4 (rows) x 2 (cols); WM = MT*16, WN = 80.
// A rows chunk-mapped (a_cr,a_cs). C rows chunk-mapped (c_cr,c_cs).
// EPI 0: v=acc  1: v=sig(acc+aux0[n])  2: v=aux1[ci]+aux2[li]*acc
// EPI 3: s=sig(acc+aux0[n]); v=s*aux1[li]+(1-s)*aux2[li]
// SPLIT: additionally write dense bf16 hi/lo of v at li.
template<int BM, int MT, int EPI, bool SPLIT>
__global__ void __launch_bounds__(256, 2)
mma_gemm(const bf16* __restrict__ Ah, const bf16* __restrict__ Al,
         const bf16* __restrict__ Wh, const bf16* __restrict__ Wl,
         float* __restrict__ C, bf16* __restrict__ Shi, bf16* __restrict__ Slo,
         int N, int K, int a_cr, long long a_cs, int c_cr, long long c_cs,
         const float* __restrict__ aux0, const float* __restrict__ aux1,
         const float* __restrict__ aux2) {
    constexpr int WM = MT * 16;                   // 4 row-warps cover BM
    constexpr int A_ROWB = BKT * 2 + 16;          // 80B
    constexpr int B_ROWB = BN * 2 + 16;           // 336B
    constexpr int A_TILE = BM * A_ROWB;
    constexpr int B_TILE = BKT * B_ROWB;
    constexpr int STAGE = 2 * A_TILE + 2 * B_TILE;

    extern __shared__ char smem_raw[];
    const uint32_t sbase = (uint32_t)__cvta_generic_to_shared(smem_raw);

    const int tid = threadIdx.x;
    const int m0 = blockIdx.y * BM, n0 = blockIdx.x * BN;
    const int warp = tid >> 5, lane = tid & 31;
    const int wid_m = warp >> 1, wid_n = warp & 1;
    const long long arow0 = (long long)(m0 / a_cr) * a_cs + (m0 % a_cr);

    float acc[MT][NT][4];
#pragma unroll
    for (int i = 0; i < MT; ++i)
#pragma unroll
        for (int j = 0; j < NT; ++j)
#pragma unroll
            for (int e = 0; e < 4; ++e) acc[i][j][e] = 0.0f;

    const int NKI = K / BKT;

    auto ldst = [&](int ks, int st) {
        const int k0 = ks * BKT;
        const uint32_t sb = sbase + st * STAGE;
#pragma unroll
        for (int t = 0; t < (BM * 4) / 256; ++t) {
            const int c = tid + t * 256;
            const int r = c >> 2, kc = (c & 3) * 8;
            const uint32_t off = r * A_ROWB + kc * 2;
            const long long gi = (arow0 + r) * (long long)K + k0 + kc;
            cp16(sb + off, Ah + gi);
            cp16(sb + A_TILE + off, Al + gi);
        }
        for (int c = tid; c < 640; c += 256) {
            const int r = c / 20, nc = c % 20;
            const uint32_t off = 2 * A_TILE + r * B_ROWB + nc * 16;
            const long long gi = (long long)(k0 + r) * N + n0 + nc * 8;
            cp16(sb + off, Wh + gi);
            cp16(sb + B_TILE + off, Wl + gi);
        }
        asm volatile("cp.async.commit_group;\n");
    };

    ldst(0, 0);
    ldst(1, 1);

    for (int ks = 0; ks < NKI; ++ks) {
        if (ks < NKI - 1) asm volatile("cp.async.wait_group 1;\n");
        else              asm volatile("cp.async.wait_group 0;\n");
        __syncthreads();
        const uint32_t sb = sbase + (ks & 1) * STAGE;

#pragma unroll
        for (int kk = 0; kk < BKT; kk += 16) {
            uint32_t ah[MT][4], al[MT][4], b[NT][2];
            const int arow = wid_m * WM + (lane & 15);
            const int acol = kk + (lane >> 4) * 8;
#pragma unroll
            for (int i = 0; i < MT; ++i) {
                const uint32_t ad = sb + (arow + i * 16) * A_ROWB + acol * 2;
                ldsm4(ah[i][0], ah[i][1], ah[i][2], ah[i][3], ad);
                ldsm4(al[i][0], al[i][1], al[i][2], al[i][3], ad + A_TILE);
            }
            const int brow = kk + (lane & 15);
            const uint32_t bbase = sb + 2 * A_TILE + brow * B_ROWB;
            // --- bh pass: ah@bh + al@bh ---
#pragma unroll
            for (int j2 = 0; j2 < 5; ++j2) {
                const int bcol = wid_n * WN + j2 * 16 + (lane >> 4) * 8;
                ldsm4t(b[2*j2][0], b[2*j2][1], b[2*j2+1][0], b[2*j2+1][1],
                       bbase + bcol * 2);
            }
#pragma unroll
            for (int i = 0; i < MT; ++i)
#pragma unroll
                for (int j = 0; j < NT; ++j) {
                    mma16816(acc[i][j], ah[i], b[j]);
                    mma16816(acc[i][j], al[i], b[j]);
                }
            // --- bl pass: ah@bl (reuse b registers) ---
#pragma unroll
            for (int j2 = 0; j2 < 5; ++j2) {
                const int bcol = wid_n * WN + j2 * 16 + (lane >> 4) * 8;
                ldsm4t(b[2*j2][0], b[2*j2][1], b[2*j2+1][0], b[2*j2+1][1],
                       bbase + B_TILE + bcol * 2);
            }
#pragma unroll
            for (int i = 0; i < MT; ++i)
#pragma unroll
                for (int j = 0; j < NT; ++j)
                    mma16816(acc[i][j], ah[i], b[j]);
        }
        __syncthreads();
        if (ks + 2 < NKI) ldst(ks + 2, ks & 1);
    }

    const int gid = lane >> 2, tig = lane & 3;
    const long long crow0 = (long long)(m0 / c_cr) * c_cs + (m0 % c_cr);

#pragma unroll
    for (int i = 0; i < MT; ++i) {
        const int r = wid_m * WM + i * 16 + gid;
#pragma unroll
        for (int j = 0; j < NT; ++j) {
            const int col = n0 + wid_n * WN + j * 8 + 2 * tig;
#pragma unroll
            for (int half = 0; half < 2; ++half) {
                const int rr = r + half * 8;
                const long long ci = (crow0 + rr) * (long long)N + col;
                const long long li = (long long)(m0 + rr) * N + col;
                float2 v;
#pragma unroll
                for (int e = 0; e < 2; ++e) {
                    const float a = acc[i][j][2 * half + e];
                    float o;
                    if      (EPI == 0) o = a;
                    else if (EPI == 1) o = sig_(a + aux0[col + e]);
                    else if (EPI == 2) o = aux1[ci + e] + aux2[li + e] * a;
                    else { const float s = sig_(a + aux0[col + e]);
                           o = s * aux1[li + e] + (1.0f - s) * aux2[li + e]; }
                    (&v.x)[e] = o;
                }
                *reinterpret_cast<float2*>(C + ci) = v;
                if (SPLIT) {
                    const bf16 h0 = __float2bfloat16(v.x), h1 = __float2bfloat16(v.y);
                    *reinterpret_cast<__nv_bfloat162*>(Shi + li) = __nv_bfloat162(h0, h1);
                    *reinterpret_cast<__nv_bfloat162*>(Slo + li) = __nv_bfloat162(
                        __float2bfloat16(v.x - __bfloat162float(h0)),
                        __float2bfloat16(v.y - __bfloat162float(h1)));
                }
            }
        }
    }
}

// ---- flash attention: 16 queries/block, warp w owns queries 2w, 2w+1 -------
__global__ void __launch_bounds__(256)
attn16(const float* __restrict__ Q, const float* __restrict__ Kp,
       const float* __restrict__ V, bf16* __restrict__ Ohi, bf16* __restrict__ Olo,
       int Lq, int Lk, float scale) {
    __shared__ float Ks[16][HDIM], Vs[16][HDIM];
    const int h = blockIdx.y, b = blockIdx.z, q0 = blockIdx.x * 16;
    const int tid = threadIdx.x, w = tid >> 5, l = tid & 31;
    const int qa = q0 + 2 * w;

    float qA[10], qB[10];
    const float* Qb = Q + ((long long)(b * Lq + qa)) * DD + h * HDIM;
#pragma unroll
    for (int t = 0; t < 10; ++t) { qA[t] = Qb[l + 32 * t]; qB[t] = Qb[DD + l + 32 * t]; }

    float mrun = -1e30f, sA = 0.0f, sB = 0.0f, accA[10], accB[10];
#pragma unroll
    for (int t = 0; t < 10; ++t) { accA[t] = 0.0f; accB[t] = 0.0f; }

    for (int c = 0; c < Lk / 16; ++c) {
        const long long k0 = (long long)(b * Lk + c * 16) * DD + h * HDIM;
#pragma unroll
        for (int t = 0; t < 5; ++t) {
            const int idx = tid + t * 256;
            const int row = idx / 80, c4 = idx % 80;
            *reinterpret_cast<float4*>(&Ks[row][c4 * 4]) =
                *reinterpret_cast<const float4*>(Kp + k0 + (long long)row * DD + c4 * 4);
            *reinterpret_cast<float4*>(&Vs[row][c4 * 4]) =
                *reinterpret_cast<const float4*>(V + k0 + (long long)row * DD + c4 * 4);
        }
        __syncthreads();
        float scA[16], scB[16], cmax = -1e30f;
#pragma unroll
        for (int k = 0; k < 16; ++k) {
            float da = 0.0f, db = 0.0f;
#pragma unroll
            for (int t = 0; t < 10; ++t) {
                const float kv = Ks[k][l + 32 * t];
                da += qA[t] * kv; db += qB[t] * kv;
            }
#pragma unroll
            for (int o = 16; o > 0; o >>= 1) {
                da += __shfl_xor_sync(0xFFFFFFFF, da, o);
                db += __shfl_xor_sync(0xFFFFFFFF, db, o);
            }
            scA[k] = da * scale; scB[k] = db * scale;
            cmax = fmaxf(cmax, fmaxf(scA[k], scB[k]));
        }
        const float mn = fmaxf(mrun, cmax);
        const float cr = __expf(mrun - mn);
        sA *= cr; sB *= cr;
#pragma unroll
        for (int t = 0; t < 10; ++t) { accA[t] *= cr; accB[t] *= cr; }
        mrun = mn;
#pragma unroll
        for (int k = 0; k < 16; ++k) {
            const float pa = __expf(scA[k] - mn), pb = __expf(scB[k] - mn);
            sA += pa; sB += pb;
#pragma unroll
            for (int t = 0; t < 10; ++t) {
                const float vv = Vs[k][l + 32 * t];
                accA[t] += pa * vv; accB[t] += pb * vv;
            }
        }
        __syncthreads();
    }
    const float iA = 1.0f / sA, iB = 1.0f / sB;
    bf16* Oh = Ohi + ((long long)(b * Lq + qa)) * DD + h * HDIM;
    bf16* Ol = Olo + ((long long)(b * Lq + qa)) * DD + h * HDIM;
#pragma unroll
    for (int t = 0; t < 10; ++t) {
        const float va = accA[t] * iA, vb = accB[t] * iB;
        const bf16 ha = __float2bfloat16(va), hb = __float2bfloat16(vb);
        Oh[l + 32 * t] = ha;      Ol[l + 32 * t] = __float2bfloat16(va - __bfloat162float(ha));
        Oh[DD + l + 32 * t] = hb; Ol[DD + l + 32 * t] = __float2bfloat16(vb - __bfloat162float(hb));
    }
}

struct WSrc { const float* p[11]; };

__global__ void wsplit_all(WSrc ws, bf16* __restrict__ hi, bf16* __restrict__ lo) {
    const int mat = blockIdx.y;
    const long long o = (long long)mat * WMAT + (long long)blockIdx.x * 256 + threadIdx.x;
    const float v = ws.p[mat][(long long)blockIdx.x * 256 + threadIdx.x];
    const bf16 h = __float2bfloat16(v);
    hi[o] = h; lo[o] = __float2bfloat16(v - __bfloat162float(h));
}

__global__ void split_id(const float* __restrict__ x, bf16* __restrict__ hi,
                         bf16* __restrict__ lo) {
    const long long o = (long long)blockIdx.x * 256 + threadIdx.x;
    const float v = x[o];
    const bf16 h = __float2bfloat16(v);
    hi[o] = h; lo[o] = __float2bfloat16(v - __bfloat162float(h));
}

__global__ void concat_split(const float* __restrict__ mem, const float* __restrict__ nm,
                             bf16* __restrict__ hi, bf16* __restrict__ lo) {
    const long long idx = (long long)blockIdx.x * 256 + threadIdx.x;
    const long long r = idx / (2 * DD);
    const int c = (int)(idx % (2 * DD));
    const float v = (c < DD) ? mem[r * DD + c] : nm[r * DD + c - DD];
    const bf16 h = __float2bfloat16(v);
    hi[idx] = h; lo[idx] = __float2bfloat16(v - __bfloat162float(h));
}

extern "C" void kernel_launch(void* const* d_in, const int* in_sizes, int n_in,
                              void* d_out, int out_size) {
    const float* hid      = (const float*)d_in[0];
    const float* init_mem = (const float*)d_in[1];
    const float* wq_r = (const float*)d_in[2];
    const float* wk_r = (const float*)d_in[3];
    const float* wv_r = (const float*)d_in[4];
    const float* wo_r = (const float*)d_in[5];
    const float* wg_r = (const float*)d_in[6];
    const float* bg_r = (const float*)d_in[7];
    const float* wqueries = (const float*)d_in[8];
    const float* wq_w = (const float*)d_in[9];
    const float* wk_w = (const float*)d_in[10];
    const float* wv_w = (const float*)d_in[11];
    const float* wo_w = (const float*)d_in[12];
    const float* wg_w = (const float*)d_in[13];
    const float* bg_w = (const float*)d_in[14];
    float* out = (float*)d_out;

    float *qr, *gate, *kw, *vw, *kr, *vr, *qw, *nm, *memA, *memB;
    bf16 *whi, *wlo, *hidhi, *hidlo, *chi, *clo, *ahi, *alo, *awhi, *awlo;
    bf16 *cathi, *catlo, *mAhi, *mAlo, *mBhi, *mBlo, *imhi, *imlo, *wqhi, *wqlo;
    cudaGetSymbolAddress((void**)&qr, g_qr);     cudaGetSymbolAddress((void**)&gate, g_gate);
    cudaGetSymbolAddress((void**)&kw, g_kw);     cudaGetSymbolAddress((void**)&vw, g_vw);
    cudaGetSymbolAddress((void**)&kr, g_kr);     cudaGetSymbolAddress((void**)&vr, g_vr);
    cudaGetSymbolAddress((void**)&qw, g_qw);     cudaGetSymbolAddress((void**)&nm, g_nm);
    cudaGetSymbolAddress((void**)&memA, g_memA); cudaGetSymbolAddress((void**)&memB, g_memB);
    cudaGetSymbolAddress((void**)&whi, g_whi);   cudaGetSymbolAddress((void**)&wlo, g_wlo);
    cudaGetSymbolAddress((void**)&hidhi, g_hidhi); cudaGetSymbolAddress((void**)&hidlo, g_hidlo);
    cudaGetSymbolAddress((void**)&chi, g_chi);   cudaGetSymbolAddress((void**)&clo, g_clo);
    cudaGetSymbolAddress((void**)&ahi, g_ahi);   cudaGetSymbolAddress((void**)&alo, g_alo);
    cudaGetSymbolAddress((void**)&awhi, g_awhi); cudaGetSymbolAddress((void**)&awlo, g_awlo);
    cudaGetSymbolAddress((void**)&cathi, g_cathi); cudaGetSymbolAddress((void**)&catlo, g_catlo);
    cudaGetSymbolAddress((void**)&mAhi, g_mAhi); cudaGetSymbolAddress((void**)&mAlo, g_mAlo);
    cudaGetSymbolAddress((void**)&mBhi, g_mBhi); cudaGetSymbolAddress((void**)&mBlo, g_mBlo);
    cudaGetSymbolAddress((void**)&imhi, g_imhi); cudaGetSymbolAddress((void**)&imlo, g_imlo);
    cudaGetSymbolAddress((void**)&wqhi, g_wqhi); cudaGetSymbolAddress((void**)&wqlo, g_wqlo);

    constexpr int SMEM_BIG = 2 * (2 * 128 * 80 + 2 * 32 * 336);   // 83968
    constexpr int SMEM_SM  = 2 * (2 * 64  * 80 + 2 * 32 * 336);   // 63488
    cudaFuncSetAttribute(mma_gemm<128,2,0,false>, cudaFuncAttributeMaxDynamicSharedMemorySize, SMEM_BIG);
    cudaFuncSetAttribute(mma_gemm<128,2,1,false>, cudaFuncAttributeMaxDynamicSharedMemorySize, SMEM_BIG);
    cudaFuncSetAttribute(mma_gemm<128,2,2,true >, cudaFuncAttributeMaxDynamicSharedMemorySize, SMEM_BIG);
    cudaFuncSetAttribute(mma_gemm<64,1,0,false>,  cudaFuncAttributeMaxDynamicSharedMemorySize, SMEM_SM);
    cudaFuncSetAttribute(mma_gemm<64,1,0,true >,  cudaFuncAttributeMaxDynamicSharedMemorySize, SMEM_SM);
    cudaFuncSetAttribute(mma_gemm<64,1,3,true >,  cudaFuncAttributeMaxDynamicSharedMemorySize, SMEM_SM);

    const float scale = 0.05590169943749474f;
    const size_t memBytesF = (size_t)MMEM * DD * sizeof(float);
    dim3 gBig(DD / BN, MBIG / 128);   // (16,16) = 256 blocks -> 1 wave
    dim3 gSm (DD / BN, MSM / 64);     // (16,4)
    dim3 gQw (DD / BN, 1);

    WSrc ws;
    ws.p[0] = wq_r; ws.p[1] = wk_r; ws.p[2] = wv_r; ws.p[3] = wo_r; ws.p[4] = wg_r;
    ws.p[5] = wq_w; ws.p[6] = wk_w; ws.p[7] = wv_w; ws.p[8] = wo_w;
    ws.p[9] = wg_w; ws.p[10] = wg_w + (long long)WMAT;
    wsplit_all<<<dim3(WMAT/256, 11), 256>>>(ws, whi, wlo);

    split_id<<<(BATCH*STOT*DD)/256,256>>>(hid, hidhi, hidlo);
    split_id<<<(MMEM*DD)/256,256>>>(init_mem, imhi, imlo);
    split_id<<<(MMEM*DD)/256,256>>>(wqueries, wqhi, wqlo);

    // qw = write_queries @ wq_w (M=128), duplicate for batch
    mma_gemm<128,2,0,false><<<gQw,256,SMEM_BIG>>>(wqhi, wqlo, whi+OW_QW, wlo+OW_QW,
        qw, nullptr, nullptr, DD, DD, MMEM, 0, MMEM, 0, nullptr, nullptr, nullptr);
    cudaMemcpyAsync(qw + (size_t)MMEM*DD, qw, memBytesF, cudaMemcpyDeviceToDevice, 0);

    float* memf[2] = {memA, memB};
    bf16*  memh[2] = {mAhi, mBhi};
    bf16*  meml[2] = {mAlo, mBlo};
    int cur = 0;

    for (int i = 0; i < NSEG; ++i) {
        const float* segp = hid + (long long)i * SEGL * DD;
        float* outp = out + (long long)i * SEGL * DD;
        const bf16* shi = hidhi + (long long)i * SEGL * DD;
        const bf16* slo = hidlo + (long long)i * SEGL * DD;

        mma_gemm<128,2,0,false><<<gBig,256,SMEM_BIG>>>(shi, slo, whi+OW_QR, wlo+OW_QR,
            qr, nullptr, nullptr, DD, DD, SEGL, (long long)STOT, MBIG, 0, nullptr, nullptr, nullptr);
        mma_gemm<128,2,1,false><<<gBig,256,SMEM_BIG>>>(shi, slo, whi+OW_GR, wlo+OW_GR,
            gate, nullptr, nullptr, DD, DD, SEGL, (long long)STOT, MBIG, 0, bg_r, nullptr, nullptr);

        const bf16* mh = (i == 0) ? imhi : memh[cur];
        const bf16* ml = (i == 0) ? imlo : meml[cur];
        const int mcr = (i == 0) ? MMEM : MSM;
        mma_gemm<64,1,0,false><<<gSm,256,SMEM_SM>>>(mh, ml, whi+OW_KR, wlo+OW_KR,
            kr, nullptr, nullptr, DD, DD, mcr, 0, MSM, 0, nullptr, nullptr, nullptr);
        mma_gemm<64,1,0,false><<<gSm,256,SMEM_SM>>>(mh, ml, whi+OW_VR, wlo+OW_VR,
            vr, nullptr, nullptr, DD, DD, mcr, 0, MSM, 0, nullptr, nullptr, nullptr);

        attn16<<<dim3(SEGL/16, NH, BATCH),256>>>(qr, kr, vr, chi, clo, SEGL, MMEM, scale);

        mma_gemm<128,2,2,true><<<gBig,256,SMEM_BIG>>>(chi, clo, whi+OW_OR, wlo+OW_OR,
            outp, ahi, alo, DD, DD, MBIG, 0, SEGL, (long long)STOT, nullptr, segp, gate);

        mma_gemm<128,2,0,false><<<gBig,256,SMEM_BIG>>>(ahi, alo, whi+OW_KW, wlo+OW_KW,
            kw, nullptr, nullptr, DD, DD, MBIG, 0, MBIG, 0, nullptr, nullptr, nullptr);
        mma_gemm<128,2,0,false><<<gBig,256,SMEM_BIG>>>(ahi, alo, whi+OW_VW, wlo+OW_VW,
            vw, nullptr, nullptr, DD, DD, MBIG, 0, MBIG, 0, nullptr, nullptr, nullptr);

        attn16<<<dim3(MMEM/16, NH, BATCH),256>>>(qw, kw, vw, awhi, awlo, MMEM, SEGL, scale);

        if (i == 0) {
            mma_gemm<64,1,0,true><<<gSm,256,SMEM_SM>>>(awhi, awlo, whi+OW_OW, wlo+OW_OW,
                memf[0], mAhi, mAlo, DD, DD, MSM, 0, MSM, 0, nullptr, nullptr, nullptr);
            cur = 0;
        } else {
            mma_gemm<64,1,0,false><<<gSm,256,SMEM_SM>>>(awhi, awlo, whi+OW_OW, wlo+OW_OW,
                nm, nullptr, nullptr, DD, DD, MSM, 0, MSM, 0, nullptr, nullptr, nullptr);
            const int nxt = cur ^ 1;
            concat_split<<<(MSM*2*DD)/256,256>>>(memf[cur], nm, cathi, catlo);
            mma_gemm<64,1,3,true><<<gSm,256,SMEM_SM>>>(cathi, catlo, whi+OW_GW, wlo+OW_GW,
                memf[nxt], memh[nxt], meml[nxt], DD, 2*DD, MSM, 0, MSM, 0,
                bg_w, nm, memf[cur]);
            cur = nxt;
        }
    }
}